// round 6
// baseline (speedup 1.0000x reference)
#include <cuda_runtime.h>
#include <cuda_fp16.h>
#include <cstdint>
#include <cstddef>

typedef __half f16;
#define DI __device__ __forceinline__

constexpr int Bn = 4, Pn = 1024, Xn = 8192, Cn = 1024;
// symmetric fold: q *= S32, k *= c * S32  ->  q.k carries 1/32 = 1/sqrt(C)
#define S32 0.1767766952966369f

// ---------------- scratch (device globals, no allocation) ----------------
__device__ f16   g_qh[(size_t)Bn * Pn * Cn];
__device__ f16   g_ql[(size_t)Bn * Pn * Cn];
__device__ f16   g_kh[(size_t)Bn * Xn * Cn];
__device__ f16   g_kl[(size_t)Bn * Xn * Cn];
__device__ f16   g_v [(size_t)Bn * Xn * Cn];
__device__ f16   g_vt[(size_t)Bn * Cn * Xn];
__device__ float g_S [(size_t)Bn * Pn * Xn];
__device__ f16   g_W [(size_t)Bn * Pn * Xn];

// ---------------- PTX helpers ----------------
DI void cp_async16(uint32_t saddr, const void* gptr) {
    asm volatile("cp.async.cg.shared.global [%0], [%1], 16;\n" :: "r"(saddr), "l"(gptr));
}
DI void cp_commit() { asm volatile("cp.async.commit_group;\n"); }
template <int N> DI void cp_wait() { asm volatile("cp.async.wait_group %0;\n" :: "n"(N)); }

DI void ldsm4(uint32_t addr, uint32_t& r0, uint32_t& r1, uint32_t& r2, uint32_t& r3) {
    asm volatile("ldmatrix.sync.aligned.m8n8.x4.shared.b16 {%0,%1,%2,%3}, [%4];\n"
                 : "=r"(r0), "=r"(r1), "=r"(r2), "=r"(r3) : "r"(addr));
}
DI void mma16816(float c[4], const uint32_t a[4], const uint32_t b[2]) {
    asm volatile(
        "mma.sync.aligned.m16n8k16.row.col.f32.f16.f16.f32 "
        "{%0,%1,%2,%3}, {%4,%5,%6,%7}, {%8,%9}, {%0,%1,%2,%3};\n"
        : "+f"(c[0]), "+f"(c[1]), "+f"(c[2]), "+f"(c[3])
        : "r"(a[0]), "r"(a[1]), "r"(a[2]), "r"(a[3]), "r"(b[0]), "r"(b[1]));
}

// Swizzled byte offset inside a 128-row x 64-col f16 tile (128B rows, SW128 XOR).
DI uint32_t swz(int r, int c8) { return (uint32_t)(r * 128 + ((c8 ^ (r & 7)) << 4)); }

// ---------------- LayerNorm -> f16 (optionally hi/lo split), C = 1024 ----------------
__global__ void __launch_bounds__(256) ln_kernel(
    const float* __restrict__ src, f16* __restrict__ dst_h, f16* __restrict__ dst_l,
    const float* __restrict__ gamma, const float* __restrict__ beta,
    const float* __restrict__ cscale, float sconst)
{
    const int row = blockIdx.x;
    const int t = threadIdx.x;
    const float4* s4 = reinterpret_cast<const float4*>(src) + (size_t)row * 256;
    float4 x = s4[t];
    float sum = x.x + x.y + x.z + x.w;
    float sq  = fmaf(x.x, x.x, fmaf(x.y, x.y, fmaf(x.z, x.z, x.w * x.w)));
#pragma unroll
    for (int o = 16; o; o >>= 1) {
        sum += __shfl_xor_sync(0xffffffffu, sum, o);
        sq  += __shfl_xor_sync(0xffffffffu, sq,  o);
    }
    __shared__ float s_sum[8], s_sq[8];
    if ((t & 31) == 0) { s_sum[t >> 5] = sum; s_sq[t >> 5] = sq; }
    __syncthreads();
    sum = 0.f; sq = 0.f;
#pragma unroll
    for (int i = 0; i < 8; i++) { sum += s_sum[i]; sq += s_sq[i]; }
    const float mu  = sum * (1.f / 1024.f);
    const float var = sq * (1.f / 1024.f) - mu * mu;
    const float rs  = rsqrtf(var + 1e-5f);
    const float sc  = (cscale ? __ldg(cscale + row) : 1.f) * sconst;

    const float4 g = reinterpret_cast<const float4*>(gamma)[t];
    const float4 b = reinterpret_cast<const float4*>(beta)[t];
    float y[4];
    y[0] = ((x.x - mu) * rs * g.x + b.x) * sc;
    y[1] = ((x.y - mu) * rs * g.y + b.y) * sc;
    y[2] = ((x.z - mu) * rs * g.z + b.z) * sc;
    y[3] = ((x.w - mu) * rs * g.w + b.w) * sc;

    __half2 h01 = __floats2half2_rn(y[0], y[1]);
    __half2 h23 = __floats2half2_rn(y[2], y[3]);
    uint2 pk;
    pk.x = *reinterpret_cast<uint32_t*>(&h01);
    pk.y = *reinterpret_cast<uint32_t*>(&h23);
    reinterpret_cast<uint2*>(dst_h + (size_t)row * 1024)[t] = pk;

    if (dst_l) {
        float l0 = y[0] - __half2float(__low2half(h01));
        float l1 = y[1] - __half2float(__high2half(h01));
        float l2 = y[2] - __half2float(__low2half(h23));
        float l3 = y[3] - __half2float(__high2half(h23));
        __half2 l01 = __floats2half2_rn(l0, l1);
        __half2 l23 = __floats2half2_rn(l2, l3);
        uint2 pl;
        pl.x = *reinterpret_cast<uint32_t*>(&l01);
        pl.y = *reinterpret_cast<uint32_t*>(&l23);
        reinterpret_cast<uint2*>(dst_l + (size_t)row * 1024)[t] = pl;
    }
}

// ---------------- f16 transpose: [b][X][C] -> [b][C][X] ----------------
__global__ void transpose_kernel(const f16* __restrict__ src, f16* __restrict__ dst)
{
    __shared__ f16 tile[32][34];
    const int b = blockIdx.z;
    const int x0 = blockIdx.x << 5, c0 = blockIdx.y << 5;
    const f16* s = src + ((size_t)b * Xn + x0) * Cn + c0;
#pragma unroll
    for (int j = 0; j < 4; j++)
        tile[threadIdx.y + j * 8][threadIdx.x] =
            s[(size_t)(threadIdx.y + j * 8) * Cn + threadIdx.x];
    __syncthreads();
    f16* d = dst + ((size_t)b * Cn + c0) * Xn + x0;
#pragma unroll
    for (int j = 0; j < 4; j++)
        d[(size_t)(threadIdx.y + j * 8) * Xn + threadIdx.x] =
            tile[threadIdx.x][threadIdx.y + j * 8];
}

// ---------------- tiled f16 GEMM: 128x128 CTA tile, K-tiles of 64 ----------------
// SPLIT=1: C = Ah*Bh^T + Ah*Bl^T + Al*Bh^T (two-sided fp32-emulation, shared stage)
// SPLIT=0: C = A*B^T
// EPI 0: store fp32.  EPI 1: store fp32 (acc + Res).
template <int SPLIT, int STAGES, int EPI>
__global__ void __launch_bounds__(256) gemm_kernel(
    const f16* __restrict__ A0, const f16* __restrict__ A1,
    const f16* __restrict__ B0, const f16* __restrict__ B1,
    float* __restrict__ Co, const float* __restrict__ Res,
    int M, int N, int K)
{
    extern __shared__ __align__(1024) char smem_raw[];
    constexpr int TILE = 16384;                       // 128x64 f16
    constexpr int NT   = SPLIT ? 4 : 2;               // tiles per stage
    constexpr int SS   = NT * TILE;
    const int tid = threadIdx.x, lane = tid & 31, warp = tid >> 5;
    const int wm = warp & 3, wn = warp >> 2;          // 4 x 2 warp grid
    const int bN = blockIdx.x, bM = blockIdx.y, bz = blockIdx.z;

    const size_t aoff = (size_t)bz * M * K + (size_t)bM * 128 * K;
    const size_t boff = (size_t)bz * N * K + (size_t)bN * 128 * K;
    const f16* src[4];
    src[0] = A0 + aoff;
    src[1] = SPLIT ? A1 + aoff : B0 + boff;
    src[2] = SPLIT ? B0 + boff : nullptr;
    src[3] = SPLIT ? B1 + boff : nullptr;

    const uint32_t sb = (uint32_t)__cvta_generic_to_shared(smem_raw);
    const int KT = K >> 6;

    auto fill = [&](int t) {
        const int k0 = t * 64;
        const uint32_t base = sb + (uint32_t)(t % STAGES) * SS;
#pragma unroll
        for (int sec = 0; sec < NT; sec++) {
#pragma unroll
            for (int i = 0; i < 4; i++) {
                int idx = tid + i * 256; int r = idx >> 3, c8 = idx & 7;
                cp_async16(base + sec * TILE + swz(r, c8),
                           src[sec] + (size_t)r * K + k0 + c8 * 8);
            }
        }
        cp_commit();
    };

    float acc[2][8][4];
#pragma unroll
    for (int mt = 0; mt < 2; mt++)
#pragma unroll
        for (int nt = 0; nt < 8; nt++)
#pragma unroll
            for (int i = 0; i < 4; i++) acc[mt][nt][i] = 0.f;

#pragma unroll
    for (int t = 0; t < STAGES - 1; t++) fill(t);

    for (int kt = 0; kt < KT; kt++) {
        cp_wait<STAGES - 2>();
        __syncthreads();
        // refill furthest-ahead stage (that slot's reads finished last iteration)
        { const int t = kt + STAGES - 1; if (t < KT) fill(t); else cp_commit(); }

        const uint32_t base = sb + (uint32_t)(kt % STAGES) * SS;
        const uint32_t sAh = base;
        const uint32_t sAl = base + TILE;                       // SPLIT only
        const uint32_t sBh = base + (SPLIT ? 2 : 1) * TILE;
        const uint32_t sBl = base + 3 * TILE;                   // SPLIT only
#pragma unroll
        for (int kk = 0; kk < 4; kk++) {
            // B fragments
            uint32_t bh[8][2];
#pragma unroll
            for (int np = 0; np < 4; np++) {
                int r = wn * 64 + np * 16 + ((lane >> 4) << 3) + (lane & 7);
                int c8 = kk * 2 + ((lane >> 3) & 1);
                ldsm4(sBh + swz(r, c8), bh[2 * np][0], bh[2 * np][1],
                                         bh[2 * np + 1][0], bh[2 * np + 1][1]);
            }
            // A fragments
            uint32_t ah[2][4];
#pragma unroll
            for (int mt = 0; mt < 2; mt++) {
                int r = wm * 32 + mt * 16 + (lane & 15);
                int c8 = kk * 2 + (lane >> 4);
                ldsm4(sAh + swz(r, c8), ah[mt][0], ah[mt][1], ah[mt][2], ah[mt][3]);
            }
#pragma unroll
            for (int mt = 0; mt < 2; mt++)
#pragma unroll
                for (int nt = 0; nt < 8; nt++)
                    mma16816(acc[mt][nt], ah[mt], bh[nt]);

            if (SPLIT) {
                uint32_t bl[8][2];
#pragma unroll
                for (int np = 0; np < 4; np++) {
                    int r = wn * 64 + np * 16 + ((lane >> 4) << 3) + (lane & 7);
                    int c8 = kk * 2 + ((lane >> 3) & 1);
                    ldsm4(sBl + swz(r, c8), bl[2 * np][0], bl[2 * np][1],
                                             bl[2 * np + 1][0], bl[2 * np + 1][1]);
                }
#pragma unroll
                for (int mt = 0; mt < 2; mt++)
#pragma unroll
                    for (int nt = 0; nt < 8; nt++)
                        mma16816(acc[mt][nt], ah[mt], bl[nt]);

                uint32_t al[2][4];
#pragma unroll
                for (int mt = 0; mt < 2; mt++) {
                    int r = wm * 32 + mt * 16 + (lane & 15);
                    int c8 = kk * 2 + (lane >> 4);
                    ldsm4(sAl + swz(r, c8), al[mt][0], al[mt][1], al[mt][2], al[mt][3]);
                }
#pragma unroll
                for (int mt = 0; mt < 2; mt++)
#pragma unroll
                    for (int nt = 0; nt < 8; nt++)
                        mma16816(acc[mt][nt], al[mt], bh[nt]);
            }
        }
    }

    const int row0 = bM * 128 + wm * 32;
    const int col0 = bN * 128 + wn * 64;
    const int tr = lane >> 2, tc = (lane & 3) << 1;
    float* C0 = Co + (size_t)bz * M * N;
    if (EPI == 0) {
#pragma unroll
        for (int mt = 0; mt < 2; mt++)
#pragma unroll
            for (int nt = 0; nt < 8; nt++) {
                int p = row0 + mt * 16 + tr, x = col0 + nt * 8 + tc;
                *reinterpret_cast<float2*>(C0 + (size_t)p * N + x) =
                    make_float2(acc[mt][nt][0], acc[mt][nt][1]);
                *reinterpret_cast<float2*>(C0 + (size_t)(p + 8) * N + x) =
                    make_float2(acc[mt][nt][2], acc[mt][nt][3]);
            }
    } else {
        const float* R0 = Res + (size_t)bz * M * N;
#pragma unroll
        for (int mt = 0; mt < 2; mt++)
#pragma unroll
            for (int nt = 0; nt < 8; nt++) {
                int p = row0 + mt * 16 + tr, x = col0 + nt * 8 + tc;
                float2 r0 = *reinterpret_cast<const float2*>(R0 + (size_t)p * N + x);
                float2 r1 = *reinterpret_cast<const float2*>(R0 + (size_t)(p + 8) * N + x);
                *reinterpret_cast<float2*>(C0 + (size_t)p * N + x) =
                    make_float2(acc[mt][nt][0] + r0.x, acc[mt][nt][1] + r0.y);
                *reinterpret_cast<float2*>(C0 + (size_t)(p + 8) * N + x) =
                    make_float2(acc[mt][nt][2] + r1.x, acc[mt][nt][3] + r1.y);
            }
    }
}

// ---------------- softmax + threshold + renorm over X=8192 ----------------
DI float blockMax(float v, float* red) {
#pragma unroll
    for (int o = 16; o; o >>= 1) v = fmaxf(v, __shfl_xor_sync(0xffffffffu, v, o));
    __syncthreads();
    if ((threadIdx.x & 31) == 0) red[threadIdx.x >> 5] = v;
    __syncthreads();
    float r = red[0];
#pragma unroll
    for (int i = 1; i < 8; i++) r = fmaxf(r, red[i]);
    return r;
}
DI float blockSum(float v, float* red) {
#pragma unroll
    for (int o = 16; o; o >>= 1) v += __shfl_xor_sync(0xffffffffu, v, o);
    __syncthreads();
    if ((threadIdx.x & 31) == 0) red[threadIdx.x >> 5] = v;
    __syncthreads();
    float r = 0.f;
#pragma unroll
    for (int i = 0; i < 8; i++) r += red[i];
    return r;
}

__global__ void __launch_bounds__(256) softmax_kernel(
    const float* __restrict__ S, f16* __restrict__ W)
{
    __shared__ float red[8];
    const size_t row = blockIdx.x;
    const int t = threadIdx.x;
    const float4* s4 = reinterpret_cast<const float4*>(S + row * Xn);
    float4 v[8];
    float m = -1e30f;
#pragma unroll
    for (int i = 0; i < 8; i++) {
        v[i] = s4[t + i * 256];
        m = fmaxf(m, fmaxf(fmaxf(v[i].x, v[i].y), fmaxf(v[i].z, v[i].w)));
    }
    m = blockMax(m, red);
    float z = 0.f;
#pragma unroll
    for (int i = 0; i < 8; i++)
        z += __expf(v[i].x - m) + __expf(v[i].y - m) +
             __expf(v[i].z - m) + __expf(v[i].w - m);
    z = blockSum(z, red);
    // p < 0.0005  <=>  s < m + ln(0.0005 * Z)
    const float thr = m + __logf(0.0005f * z);
    float z2 = 0.f;
#pragma unroll
    for (int i = 0; i < 8; i++) {
        if (v[i].x >= thr) z2 += __expf(v[i].x - m);
        if (v[i].y >= thr) z2 += __expf(v[i].y - m);
        if (v[i].z >= thr) z2 += __expf(v[i].z - m);
        if (v[i].w >= thr) z2 += __expf(v[i].w - m);
    }
    z2 = blockSum(z2, red);
    const float inv = 1.f / z2;
    uint2* wo = reinterpret_cast<uint2*>(W + row * Xn);
#pragma unroll
    for (int i = 0; i < 8; i++) {
        float w0 = (v[i].x >= thr) ? __expf(v[i].x - m) * inv : 0.f;
        float w1 = (v[i].y >= thr) ? __expf(v[i].y - m) * inv : 0.f;
        float w2 = (v[i].z >= thr) ? __expf(v[i].z - m) * inv : 0.f;
        float w3 = (v[i].w >= thr) ? __expf(v[i].w - m) * inv : 0.f;
        __half2 h01 = __floats2half2_rn(w0, w1);
        __half2 h23 = __floats2half2_rn(w2, w3);
        uint2 pk;
        pk.x = *reinterpret_cast<uint32_t*>(&h01);
        pk.y = *reinterpret_cast<uint32_t*>(&h23);
        wo[t + i * 256] = pk;
    }
}

// ---------------- launch ----------------
extern "C" void kernel_launch(void* const* d_in, const int* in_sizes, int n_in,
                              void* d_out, int out_size)
{
    const float* feat  = (const float*)d_in[0];
    const float* mem_k = (const float*)d_in[1];
    const float* mem_v = (const float*)d_in[2];
    const float* mem_c = (const float*)d_in[3];
    // d_in[4] = mem_attn (unused by reference)
    const float* gq = (const float*)d_in[5];
    const float* bq = (const float*)d_in[6];
    const float* gk = (const float*)d_in[7];
    const float* bk = (const float*)d_in[8];
    const float* gv = (const float*)d_in[9];
    const float* bv = (const float*)d_in[10];
    float* out = (float*)d_out;

    f16 *qh, *ql, *kh, *kl, *v, *vt, *W;
    float* S;
    cudaGetSymbolAddress((void**)&qh, g_qh);
    cudaGetSymbolAddress((void**)&ql, g_ql);
    cudaGetSymbolAddress((void**)&kh, g_kh);
    cudaGetSymbolAddress((void**)&kl, g_kl);
    cudaGetSymbolAddress((void**)&v,  g_v);
    cudaGetSymbolAddress((void**)&vt, g_vt);
    cudaGetSymbolAddress((void**)&S,  g_S);
    cudaGetSymbolAddress((void**)&W,  g_W);

    // smem: GEMM1 (SPLIT, 3 stages) 3*64KB = 196608 ; GEMM2 (plain, 4 stages) 4*32KB = 131072
    const int SM1 = 3 * 4 * 16384;
    const int SM2 = 4 * 2 * 16384;
    cudaFuncSetAttribute(gemm_kernel<1, 3, 0>, cudaFuncAttributeMaxDynamicSharedMemorySize, SM1);
    cudaFuncSetAttribute(gemm_kernel<0, 4, 1>, cudaFuncAttributeMaxDynamicSharedMemorySize, SM2);

    // LN: q = LN*g+b scaled 2^-2.5 (hi/lo) ; k = LN*g+b scaled c*2^-2.5 (hi/lo) ; v plain
    ln_kernel<<<Bn * Pn, 256>>>(feat,  qh, ql, gq, bq, nullptr, S32);
    ln_kernel<<<Bn * Xn, 256>>>(mem_k, kh, kl, gk, bk, mem_c,   S32);
    ln_kernel<<<Bn * Xn, 256>>>(mem_v, v, nullptr, gv, bv, nullptr, 1.f);

    transpose_kernel<<<dim3(Xn / 32, Cn / 32, Bn), dim3(32, 8)>>>(v, vt);

    // S = q @ k^T  (fp32 emulation: qh*kh + qh*kl + ql*kh; 1/sqrt(C) & confidence folded)
    gemm_kernel<1, 3, 0><<<dim3(Xn / 128, Pn / 128, Bn), 256, SM1>>>(
        qh, ql, kh, kl, S, nullptr, Pn, Xn, Cn);

    softmax_kernel<<<Bn * Pn, 256>>>(S, W);

    // out = W @ v^T + feat
    gemm_kernel<0, 4, 1><<<dim3(Cn / 128, Pn / 128, Bn), 256, SM2>>>(
        W, nullptr, vt, nullptr, out, feat, Pn, Cn, Xn);
}

// round 7
// speedup vs baseline: 1.1637x; 1.1637x over previous
#include <cuda_runtime.h>
#include <cuda_fp16.h>
#include <cstdint>
#include <cstddef>

typedef __half f16;
#define DI __device__ __forceinline__

constexpr int Bn = 4, Pn = 1024, Xn = 8192, Cn = 1024;
// symmetric fold: q *= S32, k *= c * S32  ->  q.k carries 1/32 = 1/sqrt(C)
#define S32 0.1767766952966369f

// ---------------- scratch (device globals, no allocation) ----------------
__device__ f16   g_qh[(size_t)Bn * Pn * Cn];
__device__ f16   g_ql[(size_t)Bn * Pn * Cn];
__device__ f16   g_kh[(size_t)Bn * Xn * Cn];
__device__ f16   g_kl[(size_t)Bn * Xn * Cn];   // only read by softmax repair
__device__ f16   g_v [(size_t)Bn * Xn * Cn];
__device__ f16   g_vt[(size_t)Bn * Cn * Xn];
__device__ float g_S [(size_t)Bn * Pn * Xn];
__device__ f16   g_W [(size_t)Bn * Pn * Xn];

// ---------------- PTX helpers ----------------
DI void cp_async16(uint32_t saddr, const void* gptr) {
    asm volatile("cp.async.cg.shared.global [%0], [%1], 16;\n" :: "r"(saddr), "l"(gptr));
}
DI void cp_commit() { asm volatile("cp.async.commit_group;\n"); }
template <int N> DI void cp_wait() { asm volatile("cp.async.wait_group %0;\n" :: "n"(N)); }

DI void ldsm4(uint32_t addr, uint32_t& r0, uint32_t& r1, uint32_t& r2, uint32_t& r3) {
    asm volatile("ldmatrix.sync.aligned.m8n8.x4.shared.b16 {%0,%1,%2,%3}, [%4];\n"
                 : "=r"(r0), "=r"(r1), "=r"(r2), "=r"(r3) : "r"(addr));
}
DI void mma16816(float c[4], const uint32_t a[4], const uint32_t b[2]) {
    asm volatile(
        "mma.sync.aligned.m16n8k16.row.col.f32.f16.f16.f32 "
        "{%0,%1,%2,%3}, {%4,%5,%6,%7}, {%8,%9}, {%0,%1,%2,%3};\n"
        : "+f"(c[0]), "+f"(c[1]), "+f"(c[2]), "+f"(c[3])
        : "r"(a[0]), "r"(a[1]), "r"(a[2]), "r"(a[3]), "r"(b[0]), "r"(b[1]));
}

// Swizzled byte offset inside a 128-row x 64-col f16 tile (128B rows, SW128 XOR).
DI uint32_t swz(int r, int c8) { return (uint32_t)(r * 128 + ((c8 ^ (r & 7)) << 4)); }

// ---------------- LayerNorm -> f16 (optionally hi/lo split), C = 1024 ----------------
__global__ void __launch_bounds__(256) ln_kernel(
    const float* __restrict__ src, f16* __restrict__ dst_h, f16* __restrict__ dst_l,
    const float* __restrict__ gamma, const float* __restrict__ beta,
    const float* __restrict__ cscale, float sconst)
{
    const int row = blockIdx.x;
    const int t = threadIdx.x;
    const float4* s4 = reinterpret_cast<const float4*>(src) + (size_t)row * 256;
    float4 x = s4[t];
    float sum = x.x + x.y + x.z + x.w;
    float sq  = fmaf(x.x, x.x, fmaf(x.y, x.y, fmaf(x.z, x.z, x.w * x.w)));
#pragma unroll
    for (int o = 16; o; o >>= 1) {
        sum += __shfl_xor_sync(0xffffffffu, sum, o);
        sq  += __shfl_xor_sync(0xffffffffu, sq,  o);
    }
    __shared__ float s_sum[8], s_sq[8];
    if ((t & 31) == 0) { s_sum[t >> 5] = sum; s_sq[t >> 5] = sq; }
    __syncthreads();
    sum = 0.f; sq = 0.f;
#pragma unroll
    for (int i = 0; i < 8; i++) { sum += s_sum[i]; sq += s_sq[i]; }
    const float mu  = sum * (1.f / 1024.f);
    const float var = sq * (1.f / 1024.f) - mu * mu;
    const float rs  = rsqrtf(var + 1e-5f);
    const float sc  = (cscale ? __ldg(cscale + row) : 1.f) * sconst;

    const float4 g = reinterpret_cast<const float4*>(gamma)[t];
    const float4 b = reinterpret_cast<const float4*>(beta)[t];
    float y[4];
    y[0] = ((x.x - mu) * rs * g.x + b.x) * sc;
    y[1] = ((x.y - mu) * rs * g.y + b.y) * sc;
    y[2] = ((x.z - mu) * rs * g.z + b.z) * sc;
    y[3] = ((x.w - mu) * rs * g.w + b.w) * sc;

    __half2 h01 = __floats2half2_rn(y[0], y[1]);
    __half2 h23 = __floats2half2_rn(y[2], y[3]);
    uint2 pk;
    pk.x = *reinterpret_cast<uint32_t*>(&h01);
    pk.y = *reinterpret_cast<uint32_t*>(&h23);
    reinterpret_cast<uint2*>(dst_h + (size_t)row * 1024)[t] = pk;

    if (dst_l) {
        float l0 = y[0] - __half2float(__low2half(h01));
        float l1 = y[1] - __half2float(__high2half(h01));
        float l2 = y[2] - __half2float(__low2half(h23));
        float l3 = y[3] - __half2float(__high2half(h23));
        __half2 l01 = __floats2half2_rn(l0, l1);
        __half2 l23 = __floats2half2_rn(l2, l3);
        uint2 pl;
        pl.x = *reinterpret_cast<uint32_t*>(&l01);
        pl.y = *reinterpret_cast<uint32_t*>(&l23);
        reinterpret_cast<uint2*>(dst_l + (size_t)row * 1024)[t] = pl;
    }
}

// ---------------- f16 transpose: [b][X][C] -> [b][C][X] ----------------
__global__ void transpose_kernel(const f16* __restrict__ src, f16* __restrict__ dst)
{
    __shared__ f16 tile[32][34];
    const int b = blockIdx.z;
    const int x0 = blockIdx.x << 5, c0 = blockIdx.y << 5;
    const f16* s = src + ((size_t)b * Xn + x0) * Cn + c0;
#pragma unroll
    for (int j = 0; j < 4; j++)
        tile[threadIdx.y + j * 8][threadIdx.x] =
            s[(size_t)(threadIdx.y + j * 8) * Cn + threadIdx.x];
    __syncthreads();
    f16* d = dst + ((size_t)b * Cn + c0) * Xn + x0;
#pragma unroll
    for (int j = 0; j < 4; j++)
        d[(size_t)(threadIdx.y + j * 8) * Xn + threadIdx.x] =
            tile[threadIdx.x][threadIdx.y + j * 8];
}

// ---------------- tiled f16 GEMM: 128x128 CTA tile, K-tiles of 64 ----------------
// SHB=1: C = A0*B0^T + A1*B0^T (two A sections share the B fragments)
// SHB=0: C = A0*B0^T
// EPI 0: store fp32.  EPI 1: store fp32 (acc + Res).
template <int SHB, int STAGES, int EPI>
__global__ void __launch_bounds__(256) gemm_kernel(
    const f16* __restrict__ A0, const f16* __restrict__ A1,
    const f16* __restrict__ B0,
    float* __restrict__ Co, const float* __restrict__ Res,
    int M, int N, int K)
{
    extern __shared__ __align__(1024) char smem_raw[];
    constexpr int TILE = 16384;                       // 128x64 f16
    constexpr int NT   = SHB ? 3 : 2;                 // tiles per stage
    constexpr int SS   = NT * TILE;
    const int tid = threadIdx.x, lane = tid & 31, warp = tid >> 5;
    const int wm = warp & 3, wn = warp >> 2;          // 4 x 2 warp grid
    const int bN = blockIdx.x, bM = blockIdx.y, bz = blockIdx.z;

    const size_t aoff = (size_t)bz * M * K + (size_t)bM * 128 * K;
    const size_t boff = (size_t)bz * N * K + (size_t)bN * 128 * K;
    const f16* src[3];
    src[0] = A0 + aoff;
    src[1] = SHB ? A1 + aoff : B0 + boff;
    src[2] = SHB ? B0 + boff : nullptr;

    const uint32_t sb = (uint32_t)__cvta_generic_to_shared(smem_raw);
    const int KT = K >> 6;

    auto fill = [&](int t) {
        const int k0 = t * 64;
        const uint32_t base = sb + (uint32_t)(t % STAGES) * SS;
#pragma unroll
        for (int sec = 0; sec < NT; sec++) {
#pragma unroll
            for (int i = 0; i < 4; i++) {
                int idx = tid + i * 256; int r = idx >> 3, c8 = idx & 7;
                cp_async16(base + sec * TILE + swz(r, c8),
                           src[sec] + (size_t)r * K + k0 + c8 * 8);
            }
        }
        cp_commit();
    };

    float acc[2][8][4];
#pragma unroll
    for (int mt = 0; mt < 2; mt++)
#pragma unroll
        for (int nt = 0; nt < 8; nt++)
#pragma unroll
            for (int i = 0; i < 4; i++) acc[mt][nt][i] = 0.f;

#pragma unroll
    for (int t = 0; t < STAGES - 1; t++) fill(t);

    for (int kt = 0; kt < KT; kt++) {
        cp_wait<STAGES - 2>();
        __syncthreads();
        { const int t = kt + STAGES - 1; if (t < KT) fill(t); else cp_commit(); }

        const uint32_t base = sb + (uint32_t)(kt % STAGES) * SS;
        const uint32_t sA0 = base;
        const uint32_t sA1 = base + TILE;                 // SHB only
        const uint32_t sB  = base + (SHB ? 2 : 1) * TILE;
#pragma unroll
        for (int kk = 0; kk < 4; kk++) {
            uint32_t bh[8][2];
#pragma unroll
            for (int np = 0; np < 4; np++) {
                int r = wn * 64 + np * 16 + ((lane >> 4) << 3) + (lane & 7);
                int c8 = kk * 2 + ((lane >> 3) & 1);
                ldsm4(sB + swz(r, c8), bh[2 * np][0], bh[2 * np][1],
                                        bh[2 * np + 1][0], bh[2 * np + 1][1]);
            }
            uint32_t ah[2][4];
#pragma unroll
            for (int mt = 0; mt < 2; mt++) {
                int r = wm * 32 + mt * 16 + (lane & 15);
                int c8 = kk * 2 + (lane >> 4);
                ldsm4(sA0 + swz(r, c8), ah[mt][0], ah[mt][1], ah[mt][2], ah[mt][3]);
            }
#pragma unroll
            for (int mt = 0; mt < 2; mt++)
#pragma unroll
                for (int nt = 0; nt < 8; nt++)
                    mma16816(acc[mt][nt], ah[mt], bh[nt]);

            if (SHB) {
                uint32_t al[2][4];
#pragma unroll
                for (int mt = 0; mt < 2; mt++) {
                    int r = wm * 32 + mt * 16 + (lane & 15);
                    int c8 = kk * 2 + (lane >> 4);
                    ldsm4(sA1 + swz(r, c8), al[mt][0], al[mt][1], al[mt][2], al[mt][3]);
                }
#pragma unroll
                for (int mt = 0; mt < 2; mt++)
#pragma unroll
                    for (int nt = 0; nt < 8; nt++)
                        mma16816(acc[mt][nt], al[mt], bh[nt]);
            }
        }
    }

    const int row0 = bM * 128 + wm * 32;
    const int col0 = bN * 128 + wn * 64;
    const int tr = lane >> 2, tc = (lane & 3) << 1;
    float* C0 = Co + (size_t)bz * M * N;
    if (EPI == 0) {
#pragma unroll
        for (int mt = 0; mt < 2; mt++)
#pragma unroll
            for (int nt = 0; nt < 8; nt++) {
                int p = row0 + mt * 16 + tr, x = col0 + nt * 8 + tc;
                *reinterpret_cast<float2*>(C0 + (size_t)p * N + x) =
                    make_float2(acc[mt][nt][0], acc[mt][nt][1]);
                *reinterpret_cast<float2*>(C0 + (size_t)(p + 8) * N + x) =
                    make_float2(acc[mt][nt][2], acc[mt][nt][3]);
            }
    } else {
        const float* R0 = Res + (size_t)bz * M * N;
#pragma unroll
        for (int mt = 0; mt < 2; mt++)
#pragma unroll
            for (int nt = 0; nt < 8; nt++) {
                int p = row0 + mt * 16 + tr, x = col0 + nt * 8 + tc;
                float2 r0 = *reinterpret_cast<const float2*>(R0 + (size_t)p * N + x);
                float2 r1 = *reinterpret_cast<const float2*>(R0 + (size_t)(p + 8) * N + x);
                *reinterpret_cast<float2*>(C0 + (size_t)p * N + x) =
                    make_float2(acc[mt][nt][0] + r0.x, acc[mt][nt][1] + r0.y);
                *reinterpret_cast<float2*>(C0 + (size_t)(p + 8) * N + x) =
                    make_float2(acc[mt][nt][2] + r1.x, acc[mt][nt][3] + r1.y);
            }
    }
}

// ---------------- softmax + near-threshold exact repair + sparsify + renorm ----------
DI float blockMax(float v, float* red) {
#pragma unroll
    for (int o = 16; o; o >>= 1) v = fmaxf(v, __shfl_xor_sync(0xffffffffu, v, o));
    __syncthreads();
    if ((threadIdx.x & 31) == 0) red[threadIdx.x >> 5] = v;
    __syncthreads();
    float r = red[0];
#pragma unroll
    for (int i = 1; i < 8; i++) r = fmaxf(r, red[i]);
    return r;
}
DI float blockSum(float v, float* red) {
#pragma unroll
    for (int o = 16; o; o >>= 1) v += __shfl_xor_sync(0xffffffffu, v, o);
    __syncthreads();
    if ((threadIdx.x & 31) == 0) red[threadIdx.x >> 5] = v;
    __syncthreads();
    float r = 0.f;
#pragma unroll
    for (int i = 0; i < 8; i++) r += red[i];
    return r;
}

constexpr int   FCAP  = 512;
#define DELTA 2e-3f

__global__ void __launch_bounds__(256) softmax_kernel(
    const float* __restrict__ S,
    const f16* __restrict__ qh, const f16* __restrict__ ql,
    const f16* __restrict__ kh, const f16* __restrict__ kl,
    f16* __restrict__ W)
{
    __shared__ float red[8];
    __shared__ float q_s[1024];
    __shared__ int   nf;
    __shared__ int   fx[FCAP];
    __shared__ float fsn[FCAP];

    const int row = blockIdx.x;            // b*Pn + p
    const int bz  = row >> 10;             // Pn = 1024
    const int t = threadIdx.x;
    const int lane = t & 31, warp = t >> 5;

    // preload exact q row (qh+ql) to smem
    {
        const uint2 ph = reinterpret_cast<const uint2*>(qh + (size_t)row * 1024)[t];
        const uint2 pl = reinterpret_cast<const uint2*>(ql + (size_t)row * 1024)[t];
        __half2 h0 = *reinterpret_cast<const __half2*>(&ph.x);
        __half2 h1 = *reinterpret_cast<const __half2*>(&ph.y);
        __half2 l0 = *reinterpret_cast<const __half2*>(&pl.x);
        __half2 l1 = *reinterpret_cast<const __half2*>(&pl.y);
        q_s[4 * t + 0] = __low2float(h0)  + __low2float(l0);
        q_s[4 * t + 1] = __high2float(h0) + __high2float(l0);
        q_s[4 * t + 2] = __low2float(h1)  + __low2float(l1);
        q_s[4 * t + 3] = __high2float(h1) + __high2float(l1);
    }
    if (t == 0) nf = 0;

    const float4* s4 = reinterpret_cast<const float4*>(S + (size_t)row * Xn);
    float v[8][4];
    float m = -1e30f;
#pragma unroll
    for (int i = 0; i < 8; i++) {
        float4 vv = s4[t + i * 256];
        v[i][0] = vv.x; v[i][1] = vv.y; v[i][2] = vv.z; v[i][3] = vv.w;
        m = fmaxf(m, fmaxf(fmaxf(vv.x, vv.y), fmaxf(vv.z, vv.w)));
    }
    m = blockMax(m, red);                   // also fences q_s / nf writes
    float z = 0.f;
#pragma unroll
    for (int i = 0; i < 8; i++)
#pragma unroll
        for (int j = 0; j < 4; j++) z += __expf(v[i][j] - m);
    z = blockSum(z, red);
    const float thr1 = m + __logf(0.0005f * z);

    // flag entries near the approximate threshold
#pragma unroll
    for (int i = 0; i < 8; i++)
#pragma unroll
        for (int j = 0; j < 4; j++) {
            if (fabsf(v[i][j] - thr1) < DELTA) {
                int sl = atomicAdd(&nf, 1);
                if (sl < FCAP) fx[sl] = 4 * (t + i * 256) + j;
            }
        }
    __syncthreads();
    const int nfc = min(nf, FCAP);

    // exact fp32 recompute of flagged scores: one warp per entry
    for (int e = warp; e < nfc; e += 8) {
        const int x = fx[e];
        const uint2* khp = reinterpret_cast<const uint2*>(kh + ((size_t)bz * Xn + x) * 1024);
        const uint2* klp = reinterpret_cast<const uint2*>(kl + ((size_t)bz * Xn + x) * 1024);
        float sum = 0.f;
#pragma unroll
        for (int jj = 0; jj < 8; jj++) {
            const int c4 = lane + jj * 32;
            const uint2 ph = khp[c4];
            const uint2 pl = klp[c4];
            __half2 h0 = *reinterpret_cast<const __half2*>(&ph.x);
            __half2 h1 = *reinterpret_cast<const __half2*>(&ph.y);
            __half2 l0 = *reinterpret_cast<const __half2*>(&pl.x);
            __half2 l1 = *reinterpret_cast<const __half2*>(&pl.y);
            sum = fmaf(q_s[4 * c4 + 0], __low2float(h0)  + __low2float(l0),  sum);
            sum = fmaf(q_s[4 * c4 + 1], __high2float(h0) + __high2float(l0), sum);
            sum = fmaf(q_s[4 * c4 + 2], __low2float(h1)  + __low2float(l1),  sum);
            sum = fmaf(q_s[4 * c4 + 3], __high2float(h1) + __high2float(l1), sum);
        }
#pragma unroll
        for (int o = 16; o; o >>= 1) sum += __shfl_xor_sync(0xffffffffu, sum, o);
        if (lane == 0) fsn[e] = sum;
    }
    __syncthreads();

    // patch my registers with exact scores
    for (int e = 0; e < nfc; e++) {
        const int x = fx[e];
        const int q4 = x >> 2;
        if ((q4 & 255) == t) v[q4 >> 8][x & 3] = fsn[e];
    }

    // rebuild Z and threshold from patched values (deterministic full reduction)
    float z_p = 0.f;
#pragma unroll
    for (int i = 0; i < 8; i++)
#pragma unroll
        for (int j = 0; j < 4; j++) z_p += __expf(v[i][j] - m);
    z_p = blockSum(z_p, red);
    const float thr = m + __logf(0.0005f * z_p);

    float z2 = 0.f;
#pragma unroll
    for (int i = 0; i < 8; i++)
#pragma unroll
        for (int j = 0; j < 4; j++)
            if (v[i][j] >= thr) z2 += __expf(v[i][j] - m);
    z2 = blockSum(z2, red);
    const float inv = 1.f / z2;

    uint2* wo = reinterpret_cast<uint2*>(W + (size_t)row * Xn);
#pragma unroll
    for (int i = 0; i < 8; i++) {
        float w0 = (v[i][0] >= thr) ? __expf(v[i][0] - m) * inv : 0.f;
        float w1 = (v[i][1] >= thr) ? __expf(v[i][1] - m) * inv : 0.f;
        float w2 = (v[i][2] >= thr) ? __expf(v[i][2] - m) * inv : 0.f;
        float w3 = (v[i][3] >= thr) ? __expf(v[i][3] - m) * inv : 0.f;
        __half2 h01 = __floats2half2_rn(w0, w1);
        __half2 h23 = __floats2half2_rn(w2, w3);
        uint2 pk;
        pk.x = *reinterpret_cast<uint32_t*>(&h01);
        pk.y = *reinterpret_cast<uint32_t*>(&h23);
        wo[t + i * 256] = pk;
    }
}

// ---------------- launch ----------------
extern "C" void kernel_launch(void* const* d_in, const int* in_sizes, int n_in,
                              void* d_out, int out_size)
{
    const float* feat  = (const float*)d_in[0];
    const float* mem_k = (const float*)d_in[1];
    const float* mem_v = (const float*)d_in[2];
    const float* mem_c = (const float*)d_in[3];
    // d_in[4] = mem_attn (unused by reference)
    const float* gq = (const float*)d_in[5];
    const float* bq = (const float*)d_in[6];
    const float* gk = (const float*)d_in[7];
    const float* bk = (const float*)d_in[8];
    const float* gv = (const float*)d_in[9];
    const float* bv = (const float*)d_in[10];
    float* out = (float*)d_out;

    f16 *qh, *ql, *kh, *kl, *v, *vt, *W;
    float* S;
    cudaGetSymbolAddress((void**)&qh, g_qh);
    cudaGetSymbolAddress((void**)&ql, g_ql);
    cudaGetSymbolAddress((void**)&kh, g_kh);
    cudaGetSymbolAddress((void**)&kl, g_kl);
    cudaGetSymbolAddress((void**)&v,  g_v);
    cudaGetSymbolAddress((void**)&vt, g_vt);
    cudaGetSymbolAddress((void**)&S,  g_S);
    cudaGetSymbolAddress((void**)&W,  g_W);

    // smem: GEMM1 (SHB, 4 stages) 4*48KB = 196608 ; GEMM2 (plain, 4 stages) 4*32KB = 131072
    const int SM1 = 4 * 3 * 16384;
    const int SM2 = 4 * 2 * 16384;
    cudaFuncSetAttribute(gemm_kernel<1, 4, 0>, cudaFuncAttributeMaxDynamicSharedMemorySize, SM1);
    cudaFuncSetAttribute(gemm_kernel<0, 4, 1>, cudaFuncAttributeMaxDynamicSharedMemorySize, SM2);

    // LN: q = LN*g+b scaled 2^-2.5 (hi/lo) ; k = LN*g+b scaled c*2^-2.5 (hi/lo) ; v plain
    ln_kernel<<<Bn * Pn, 256>>>(feat,  qh, ql, gq, bq, nullptr, S32);
    ln_kernel<<<Bn * Xn, 256>>>(mem_k, kh, kl, gk, bk, mem_c,   S32);
    ln_kernel<<<Bn * Xn, 256>>>(mem_v, v, nullptr, gv, bv, nullptr, 1.f);

    transpose_kernel<<<dim3(Xn / 32, Cn / 32, Bn), dim3(32, 8)>>>(v, vt);

    // S~ = (qh+ql) @ kh^T   (2 passes: qh*kh + ql*kh; k-fp16 error repaired in softmax)
    gemm_kernel<1, 4, 0><<<dim3(Xn / 128, Pn / 128, Bn), 256, SM1>>>(
        qh, ql, kh, S, nullptr, Pn, Xn, Cn);

    softmax_kernel<<<Bn * Pn, 256>>>(S, qh, ql, kh, kl, W);

    // out = W @ v^T + feat
    gemm_kernel<0, 4, 1><<<dim3(Cn / 128, Pn / 128, Bn), 256, SM2>>>(
        W, nullptr, vt, out, feat, Pn, Cn, Xn);
}

// round 8
// speedup vs baseline: 1.4107x; 1.2122x over previous
#include <cuda_runtime.h>
#include <cuda_fp16.h>
#include <cstdint>
#include <cstddef>

typedef __half f16;
#define DI __device__ __forceinline__

constexpr int Bn = 4, Pn = 1024, Xn = 8192, Cn = 1024;
// symmetric fold: q *= S32, k *= c * S32  ->  q.k carries 1/32 = 1/sqrt(C)
#define S32 0.1767766952966369f

// ---------------- scratch (device globals, no allocation) ----------------
__device__ f16   g_qh[(size_t)Bn * Pn * Cn];
__device__ f16   g_ql[(size_t)Bn * Pn * Cn];   // only read by softmax repair
__device__ f16   g_kh[(size_t)Bn * Xn * Cn];
__device__ f16   g_kl[(size_t)Bn * Xn * Cn];   // only read by softmax repair
__device__ f16   g_v [(size_t)Bn * Xn * Cn];
__device__ f16   g_vt[(size_t)Bn * Cn * Xn];
__device__ float g_S [(size_t)Bn * Pn * Xn];
__device__ f16   g_W [(size_t)Bn * Pn * Xn];

// ---------------- PTX helpers ----------------
DI void cp_async16(uint32_t saddr, const void* gptr) {
    asm volatile("cp.async.cg.shared.global [%0], [%1], 16;\n" :: "r"(saddr), "l"(gptr));
}
DI void cp_commit() { asm volatile("cp.async.commit_group;\n"); }
template <int N> DI void cp_wait() { asm volatile("cp.async.wait_group %0;\n" :: "n"(N)); }

DI void ldsm4(uint32_t addr, uint32_t& r0, uint32_t& r1, uint32_t& r2, uint32_t& r3) {
    asm volatile("ldmatrix.sync.aligned.m8n8.x4.shared.b16 {%0,%1,%2,%3}, [%4];\n"
                 : "=r"(r0), "=r"(r1), "=r"(r2), "=r"(r3) : "r"(addr));
}
DI void mma16816(float c[4], const uint32_t a[4], const uint32_t b[2]) {
    asm volatile(
        "mma.sync.aligned.m16n8k16.row.col.f32.f16.f16.f32 "
        "{%0,%1,%2,%3}, {%4,%5,%6,%7}, {%8,%9}, {%0,%1,%2,%3};\n"
        : "+f"(c[0]), "+f"(c[1]), "+f"(c[2]), "+f"(c[3])
        : "r"(a[0]), "r"(a[1]), "r"(a[2]), "r"(a[3]), "r"(b[0]), "r"(b[1]));
}

// Swizzled byte offset inside a 128-row x 64-col f16 tile (128B rows, SW128 XOR).
DI uint32_t swz(int r, int c8) { return (uint32_t)(r * 128 + ((c8 ^ (r & 7)) << 4)); }

// ---------------- LayerNorm -> f16 (optionally hi/lo split), C = 1024 ----------------
__global__ void __launch_bounds__(256) ln_kernel(
    const float* __restrict__ src, f16* __restrict__ dst_h, f16* __restrict__ dst_l,
    const float* __restrict__ gamma, const float* __restrict__ beta,
    const float* __restrict__ cscale, float sconst)
{
    const int row = blockIdx.x;
    const int t = threadIdx.x;
    const float4* s4 = reinterpret_cast<const float4*>(src) + (size_t)row * 256;
    float4 x = s4[t];
    float sum = x.x + x.y + x.z + x.w;
    float sq  = fmaf(x.x, x.x, fmaf(x.y, x.y, fmaf(x.z, x.z, x.w * x.w)));
#pragma unroll
    for (int o = 16; o; o >>= 1) {
        sum += __shfl_xor_sync(0xffffffffu, sum, o);
        sq  += __shfl_xor_sync(0xffffffffu, sq,  o);
    }
    __shared__ float s_sum[8], s_sq[8];
    if ((t & 31) == 0) { s_sum[t >> 5] = sum; s_sq[t >> 5] = sq; }
    __syncthreads();
    sum = 0.f; sq = 0.f;
#pragma unroll
    for (int i = 0; i < 8; i++) { sum += s_sum[i]; sq += s_sq[i]; }
    const float mu  = sum * (1.f / 1024.f);
    const float var = sq * (1.f / 1024.f) - mu * mu;
    const float rs  = rsqrtf(var + 1e-5f);
    const float sc  = (cscale ? __ldg(cscale + row) : 1.f) * sconst;

    const float4 g = reinterpret_cast<const float4*>(gamma)[t];
    const float4 b = reinterpret_cast<const float4*>(beta)[t];
    float y[4];
    y[0] = ((x.x - mu) * rs * g.x + b.x) * sc;
    y[1] = ((x.y - mu) * rs * g.y + b.y) * sc;
    y[2] = ((x.z - mu) * rs * g.z + b.z) * sc;
    y[3] = ((x.w - mu) * rs * g.w + b.w) * sc;

    __half2 h01 = __floats2half2_rn(y[0], y[1]);
    __half2 h23 = __floats2half2_rn(y[2], y[3]);
    uint2 pk;
    pk.x = *reinterpret_cast<uint32_t*>(&h01);
    pk.y = *reinterpret_cast<uint32_t*>(&h23);
    reinterpret_cast<uint2*>(dst_h + (size_t)row * 1024)[t] = pk;

    if (dst_l) {
        float l0 = y[0] - __half2float(__low2half(h01));
        float l1 = y[1] - __half2float(__high2half(h01));
        float l2 = y[2] - __half2float(__low2half(h23));
        float l3 = y[3] - __half2float(__high2half(h23));
        __half2 l01 = __floats2half2_rn(l0, l1);
        __half2 l23 = __floats2half2_rn(l2, l3);
        uint2 pl;
        pl.x = *reinterpret_cast<uint32_t*>(&l01);
        pl.y = *reinterpret_cast<uint32_t*>(&l23);
        reinterpret_cast<uint2*>(dst_l + (size_t)row * 1024)[t] = pl;
    }
}

// ---------------- f16 transpose: [b][X][C] -> [b][C][X] ----------------
__global__ void transpose_kernel(const f16* __restrict__ src, f16* __restrict__ dst)
{
    __shared__ f16 tile[32][34];
    const int b = blockIdx.z;
    const int x0 = blockIdx.x << 5, c0 = blockIdx.y << 5;
    const f16* s = src + ((size_t)b * Xn + x0) * Cn + c0;
#pragma unroll
    for (int j = 0; j < 4; j++)
        tile[threadIdx.y + j * 8][threadIdx.x] =
            s[(size_t)(threadIdx.y + j * 8) * Cn + threadIdx.x];
    __syncthreads();
    f16* d = dst + ((size_t)b * Cn + c0) * Xn + x0;
#pragma unroll
    for (int j = 0; j < 4; j++)
        d[(size_t)(threadIdx.y + j * 8) * Xn + threadIdx.x] =
            tile[threadIdx.x][threadIdx.y + j * 8];
}

// ---------------- tiled f16 GEMM: 128x128 CTA tile, K-tiles of 64 ----------------
// SHB=1: C = A0*B0^T + A1*B0^T (two A sections share the B fragments)
// SHB=0: C = A0*B0^T
// EPI 0: store fp32.  EPI 1: store fp32 (acc + Res).
template <int SHB, int STAGES, int EPI>
__global__ void __launch_bounds__(256) gemm_kernel(
    const f16* __restrict__ A0, const f16* __restrict__ A1,
    const f16* __restrict__ B0,
    float* __restrict__ Co, const float* __restrict__ Res,
    int M, int N, int K)
{
    extern __shared__ __align__(1024) char smem_raw[];
    constexpr int TILE = 16384;                       // 128x64 f16
    constexpr int NT   = SHB ? 3 : 2;                 // tiles per stage
    constexpr int SS   = NT * TILE;
    const int tid = threadIdx.x, lane = tid & 31, warp = tid >> 5;
    const int wm = warp & 3, wn = warp >> 2;          // 4 x 2 warp grid
    const int bN = blockIdx.x, bM = blockIdx.y, bz = blockIdx.z;

    const size_t aoff = (size_t)bz * M * K + (size_t)bM * 128 * K;
    const size_t boff = (size_t)bz * N * K + (size_t)bN * 128 * K;
    const f16* src[3];
    src[0] = A0 + aoff;
    src[1] = SHB ? A1 + aoff : B0 + boff;
    src[2] = SHB ? B0 + boff : nullptr;

    const uint32_t sb = (uint32_t)__cvta_generic_to_shared(smem_raw);
    const int KT = K >> 6;

    auto fill = [&](int t) {
        const int k0 = t * 64;
        const uint32_t base = sb + (uint32_t)(t % STAGES) * SS;
#pragma unroll
        for (int sec = 0; sec < NT; sec++) {
#pragma unroll
            for (int i = 0; i < 4; i++) {
                int idx = tid + i * 256; int r = idx >> 3, c8 = idx & 7;
                cp_async16(base + sec * TILE + swz(r, c8),
                           src[sec] + (size_t)r * K + k0 + c8 * 8);
            }
        }
        cp_commit();
    };

    float acc[2][8][4];
#pragma unroll
    for (int mt = 0; mt < 2; mt++)
#pragma unroll
        for (int nt = 0; nt < 8; nt++)
#pragma unroll
            for (int i = 0; i < 4; i++) acc[mt][nt][i] = 0.f;

#pragma unroll
    for (int t = 0; t < STAGES - 1; t++) fill(t);

    for (int kt = 0; kt < KT; kt++) {
        cp_wait<STAGES - 2>();
        __syncthreads();
        { const int t = kt + STAGES - 1; if (t < KT) fill(t); else cp_commit(); }

        const uint32_t base = sb + (uint32_t)(kt % STAGES) * SS;
        const uint32_t sA0 = base;
        const uint32_t sA1 = base + TILE;                 // SHB only
        const uint32_t sB  = base + (SHB ? 2 : 1) * TILE;
#pragma unroll
        for (int kk = 0; kk < 4; kk++) {
            uint32_t bh[8][2];
#pragma unroll
            for (int np = 0; np < 4; np++) {
                int r = wn * 64 + np * 16 + ((lane >> 4) << 3) + (lane & 7);
                int c8 = kk * 2 + ((lane >> 3) & 1);
                ldsm4(sB + swz(r, c8), bh[2 * np][0], bh[2 * np][1],
                                        bh[2 * np + 1][0], bh[2 * np + 1][1]);
            }
            uint32_t ah[2][4];
#pragma unroll
            for (int mt = 0; mt < 2; mt++) {
                int r = wm * 32 + mt * 16 + (lane & 15);
                int c8 = kk * 2 + (lane >> 4);
                ldsm4(sA0 + swz(r, c8), ah[mt][0], ah[mt][1], ah[mt][2], ah[mt][3]);
            }
#pragma unroll
            for (int mt = 0; mt < 2; mt++)
#pragma unroll
                for (int nt = 0; nt < 8; nt++)
                    mma16816(acc[mt][nt], ah[mt], bh[nt]);

            if (SHB) {
                uint32_t al[2][4];
#pragma unroll
                for (int mt = 0; mt < 2; mt++) {
                    int r = wm * 32 + mt * 16 + (lane & 15);
                    int c8 = kk * 2 + (lane >> 4);
                    ldsm4(sA1 + swz(r, c8), al[mt][0], al[mt][1], al[mt][2], al[mt][3]);
                }
#pragma unroll
                for (int mt = 0; mt < 2; mt++)
#pragma unroll
                    for (int nt = 0; nt < 8; nt++)
                        mma16816(acc[mt][nt], al[mt], bh[nt]);
            }
        }
    }

    const int row0 = bM * 128 + wm * 32;
    const int col0 = bN * 128 + wn * 64;
    const int tr = lane >> 2, tc = (lane & 3) << 1;
    float* C0 = Co + (size_t)bz * M * N;
    if (EPI == 0) {
#pragma unroll
        for (int mt = 0; mt < 2; mt++)
#pragma unroll
            for (int nt = 0; nt < 8; nt++) {
                int p = row0 + mt * 16 + tr, x = col0 + nt * 8 + tc;
                *reinterpret_cast<float2*>(C0 + (size_t)p * N + x) =
                    make_float2(acc[mt][nt][0], acc[mt][nt][1]);
                *reinterpret_cast<float2*>(C0 + (size_t)(p + 8) * N + x) =
                    make_float2(acc[mt][nt][2], acc[mt][nt][3]);
            }
    } else {
        const float* R0 = Res + (size_t)bz * M * N;
#pragma unroll
        for (int mt = 0; mt < 2; mt++)
#pragma unroll
            for (int nt = 0; nt < 8; nt++) {
                int p = row0 + mt * 16 + tr, x = col0 + nt * 8 + tc;
                float2 r0 = *reinterpret_cast<const float2*>(R0 + (size_t)p * N + x);
                float2 r1 = *reinterpret_cast<const float2*>(R0 + (size_t)(p + 8) * N + x);
                *reinterpret_cast<float2*>(C0 + (size_t)p * N + x) =
                    make_float2(acc[mt][nt][0] + r0.x, acc[mt][nt][1] + r0.y);
                *reinterpret_cast<float2*>(C0 + (size_t)(p + 8) * N + x) =
                    make_float2(acc[mt][nt][2] + r1.x, acc[mt][nt][3] + r1.y);
            }
    }
}

// ---------------- softmax + near-threshold exact repair + sparsify + renorm ----------
DI float blockMax(float v, float* red) {
#pragma unroll
    for (int o = 16; o; o >>= 1) v = fmaxf(v, __shfl_xor_sync(0xffffffffu, v, o));
    __syncthreads();
    if ((threadIdx.x & 31) == 0) red[threadIdx.x >> 5] = v;
    __syncthreads();
    float r = red[0];
#pragma unroll
    for (int i = 1; i < 8; i++) r = fmaxf(r, red[i]);
    return r;
}
DI float blockSum(float v, float* red) {
#pragma unroll
    for (int o = 16; o; o >>= 1) v += __shfl_xor_sync(0xffffffffu, v, o);
    __syncthreads();
    if ((threadIdx.x & 31) == 0) red[threadIdx.x >> 5] = v;
    __syncthreads();
    float r = 0.f;
#pragma unroll
    for (int i = 0; i < 8; i++) r += red[i];
    return r;
}

constexpr int   FCAP  = 768;
#define DELTA 2.5e-3f

__global__ void __launch_bounds__(256) softmax_kernel(
    const float* __restrict__ S,
    const f16* __restrict__ qh, const f16* __restrict__ ql,
    const f16* __restrict__ kh, const f16* __restrict__ kl,
    f16* __restrict__ W)
{
    __shared__ float red[8];
    __shared__ float q_s[1024];
    __shared__ int   nf;
    __shared__ int   fx[FCAP];
    __shared__ float fsn[FCAP];

    const int row = blockIdx.x;            // b*Pn + p
    const int bz  = row >> 10;             // Pn = 1024
    const int t = threadIdx.x;
    const int lane = t & 31, warp = t >> 5;

    // preload exact q row (qh+ql) to smem
    {
        const uint2 ph = reinterpret_cast<const uint2*>(qh + (size_t)row * 1024)[t];
        const uint2 pl = reinterpret_cast<const uint2*>(ql + (size_t)row * 1024)[t];
        __half2 h0 = *reinterpret_cast<const __half2*>(&ph.x);
        __half2 h1 = *reinterpret_cast<const __half2*>(&ph.y);
        __half2 l0 = *reinterpret_cast<const __half2*>(&pl.x);
        __half2 l1 = *reinterpret_cast<const __half2*>(&pl.y);
        q_s[4 * t + 0] = __low2float(h0)  + __low2float(l0);
        q_s[4 * t + 1] = __high2float(h0) + __high2float(l0);
        q_s[4 * t + 2] = __low2float(h1)  + __low2float(l1);
        q_s[4 * t + 3] = __high2float(h1) + __high2float(l1);
    }
    if (t == 0) nf = 0;

    const float4* s4 = reinterpret_cast<const float4*>(S + (size_t)row * Xn);
    float v[8][4];
    float m = -1e30f;
#pragma unroll
    for (int i = 0; i < 8; i++) {
        float4 vv = s4[t + i * 256];
        v[i][0] = vv.x; v[i][1] = vv.y; v[i][2] = vv.z; v[i][3] = vv.w;
        m = fmaxf(m, fmaxf(fmaxf(vv.x, vv.y), fmaxf(vv.z, vv.w)));
    }
    m = blockMax(m, red);                   // also fences q_s / nf writes
    float z = 0.f;
#pragma unroll
    for (int i = 0; i < 8; i++)
#pragma unroll
        for (int j = 0; j < 4; j++) z += __expf(v[i][j] - m);
    z = blockSum(z, red);
    const float thr1 = m + __logf(0.0005f * z);

    // flag entries near the approximate threshold
#pragma unroll
    for (int i = 0; i < 8; i++)
#pragma unroll
        for (int j = 0; j < 4; j++) {
            if (fabsf(v[i][j] - thr1) < DELTA) {
                int sl = atomicAdd(&nf, 1);
                if (sl < FCAP) fx[sl] = 4 * (t + i * 256) + j;
            }
        }
    __syncthreads();
    const int nfc = min(nf, FCAP);

    // exact fp32 recompute of flagged scores: one warp per entry
    for (int e = warp; e < nfc; e += 8) {
        const int x = fx[e];
        const uint2* khp = reinterpret_cast<const uint2*>(kh + ((size_t)bz * Xn + x) * 1024);
        const uint2* klp = reinterpret_cast<const uint2*>(kl + ((size_t)bz * Xn + x) * 1024);
        float sum = 0.f;
#pragma unroll
        for (int jj = 0; jj < 8; jj++) {
            const int c4 = lane + jj * 32;
            const uint2 ph = khp[c4];
            const uint2 pl = klp[c4];
            __half2 h0 = *reinterpret_cast<const __half2*>(&ph.x);
            __half2 h1 = *reinterpret_cast<const __half2*>(&ph.y);
            __half2 l0 = *reinterpret_cast<const __half2*>(&pl.x);
            __half2 l1 = *reinterpret_cast<const __half2*>(&pl.y);
            sum = fmaf(q_s[4 * c4 + 0], __low2float(h0)  + __low2float(l0),  sum);
            sum = fmaf(q_s[4 * c4 + 1], __high2float(h0) + __high2float(l0), sum);
            sum = fmaf(q_s[4 * c4 + 2], __low2float(h1)  + __low2float(l1),  sum);
            sum = fmaf(q_s[4 * c4 + 3], __high2float(h1) + __high2float(l1), sum);
        }
#pragma unroll
        for (int o = 16; o; o >>= 1) sum += __shfl_xor_sync(0xffffffffu, sum, o);
        if (lane == 0) fsn[e] = sum;
    }
    __syncthreads();

    // patch my registers with exact scores
    for (int e = 0; e < nfc; e++) {
        const int x = fx[e];
        const int q4 = x >> 2;
        if ((q4 & 255) == t) v[q4 >> 8][x & 3] = fsn[e];
    }

    // rebuild Z and threshold from patched values (deterministic full reduction)
    float z_p = 0.f;
#pragma unroll
    for (int i = 0; i < 8; i++)
#pragma unroll
        for (int j = 0; j < 4; j++) z_p += __expf(v[i][j] - m);
    z_p = blockSum(z_p, red);
    const float thr = m + __logf(0.0005f * z_p);

    float z2 = 0.f;
#pragma unroll
    for (int i = 0; i < 8; i++)
#pragma unroll
        for (int j = 0; j < 4; j++)
            if (v[i][j] >= thr) z2 += __expf(v[i][j] - m);
    z2 = blockSum(z2, red);
    const float inv = 1.f / z2;

    uint2* wo = reinterpret_cast<uint2*>(W + (size_t)row * Xn);
#pragma unroll
    for (int i = 0; i < 8; i++) {
        float w0 = (v[i][0] >= thr) ? __expf(v[i][0] - m) * inv : 0.f;
        float w1 = (v[i][1] >= thr) ? __expf(v[i][1] - m) * inv : 0.f;
        float w2 = (v[i][2] >= thr) ? __expf(v[i][2] - m) * inv : 0.f;
        float w3 = (v[i][3] >= thr) ? __expf(v[i][3] - m) * inv : 0.f;
        __half2 h01 = __floats2half2_rn(w0, w1);
        __half2 h23 = __floats2half2_rn(w2, w3);
        uint2 pk;
        pk.x = *reinterpret_cast<uint32_t*>(&h01);
        pk.y = *reinterpret_cast<uint32_t*>(&h23);
        wo[t + i * 256] = pk;
    }
}

// ---------------- launch ----------------
extern "C" void kernel_launch(void* const* d_in, const int* in_sizes, int n_in,
                              void* d_out, int out_size)
{
    const float* feat  = (const float*)d_in[0];
    const float* mem_k = (const float*)d_in[1];
    const float* mem_v = (const float*)d_in[2];
    const float* mem_c = (const float*)d_in[3];
    // d_in[4] = mem_attn (unused by reference)
    const float* gq = (const float*)d_in[5];
    const float* bq = (const float*)d_in[6];
    const float* gk = (const float*)d_in[7];
    const float* bk = (const float*)d_in[8];
    const float* gv = (const float*)d_in[9];
    const float* bv = (const float*)d_in[10];
    float* out = (float*)d_out;

    f16 *qh, *ql, *kh, *kl, *v, *vt, *W;
    float* S;
    cudaGetSymbolAddress((void**)&qh, g_qh);
    cudaGetSymbolAddress((void**)&ql, g_ql);
    cudaGetSymbolAddress((void**)&kh, g_kh);
    cudaGetSymbolAddress((void**)&kl, g_kl);
    cudaGetSymbolAddress((void**)&v,  g_v);
    cudaGetSymbolAddress((void**)&vt, g_vt);
    cudaGetSymbolAddress((void**)&S,  g_S);
    cudaGetSymbolAddress((void**)&W,  g_W);

    // smem: both GEMMs plain 2-tile stages, 4 stages: 4*32KB = 131072
    const int SM = 4 * 2 * 16384;
    cudaFuncSetAttribute(gemm_kernel<0, 4, 0>, cudaFuncAttributeMaxDynamicSharedMemorySize, SM);
    cudaFuncSetAttribute(gemm_kernel<0, 4, 1>, cudaFuncAttributeMaxDynamicSharedMemorySize, SM);

    // LN: q = LN*g+b scaled 2^-2.5 (hi/lo) ; k = LN*g+b scaled c*2^-2.5 (hi/lo) ; v plain
    ln_kernel<<<Bn * Pn, 256>>>(feat,  qh, ql, gq, bq, nullptr, S32);
    ln_kernel<<<Bn * Xn, 256>>>(mem_k, kh, kl, gk, bk, mem_c,   S32);
    ln_kernel<<<Bn * Xn, 256>>>(mem_v, v, nullptr, gv, bv, nullptr, 1.f);

    transpose_kernel<<<dim3(Xn / 32, Cn / 32, Bn), dim3(32, 8)>>>(v, vt);

    // S~ = qh @ kh^T  (single fp16 pass; near-threshold entries repaired exactly in softmax)
    gemm_kernel<0, 4, 0><<<dim3(Xn / 128, Pn / 128, Bn), 256, SM>>>(
        qh, nullptr, kh, S, nullptr, Pn, Xn, Cn);

    softmax_kernel<<<Bn * Pn, 256>>>(S, qh, ql, kh, kl, W);

    // out = W @ v^T + feat
    gemm_kernel<0, 4, 1><<<dim3(Cn / 128, Pn / 128, Bn), 256, SM>>>(
        W, nullptr, vt, out, feat, Pn, Cn, Xn);
}

// round 9
// speedup vs baseline: 1.5028x; 1.0653x over previous
#include <cuda_runtime.h>
#include <cuda_fp16.h>
#include <cstdint>
#include <cstddef>

typedef __half f16;
#define DI __device__ __forceinline__

constexpr int Bn = 4, Pn = 1024, Xn = 8192, Cn = 1024;
// symmetric fold: q *= S32, k *= c * S32  ->  q.k carries 1/32 = 1/sqrt(C)
#define S32 0.1767766952966369f

// ---------------- scratch (device globals, no allocation) ----------------
__device__ f16   g_qh[(size_t)Bn * Pn * Cn];
__device__ f16   g_ql[(size_t)Bn * Pn * Cn];   // only read by softmax repair
__device__ f16   g_kh[(size_t)Bn * Xn * Cn];
__device__ f16   g_kl[(size_t)Bn * Xn * Cn];   // only read by softmax repair
__device__ f16   g_v [(size_t)Bn * Xn * Cn];
__device__ f16   g_vt[(size_t)Bn * Cn * Xn];
__device__ f16   g_S [(size_t)Bn * Pn * Xn];   // scores f16 (repaired later)
__device__ f16   g_W [(size_t)Bn * Pn * Xn];

// ---------------- PTX helpers ----------------
DI void cp_async16(uint32_t saddr, const void* gptr) {
    asm volatile("cp.async.cg.shared.global [%0], [%1], 16;\n" :: "r"(saddr), "l"(gptr));
}
DI void cp_commit() { asm volatile("cp.async.commit_group;\n"); }
template <int N> DI void cp_wait() { asm volatile("cp.async.wait_group %0;\n" :: "n"(N)); }

DI void ldsm4(uint32_t addr, uint32_t& r0, uint32_t& r1, uint32_t& r2, uint32_t& r3) {
    asm volatile("ldmatrix.sync.aligned.m8n8.x4.shared.b16 {%0,%1,%2,%3}, [%4];\n"
                 : "=r"(r0), "=r"(r1), "=r"(r2), "=r"(r3) : "r"(addr));
}
DI void mma16816(float c[4], const uint32_t a[4], const uint32_t b[2]) {
    asm volatile(
        "mma.sync.aligned.m16n8k16.row.col.f32.f16.f16.f32 "
        "{%0,%1,%2,%3}, {%4,%5,%6,%7}, {%8,%9}, {%0,%1,%2,%3};\n"
        : "+f"(c[0]), "+f"(c[1]), "+f"(c[2]), "+f"(c[3])
        : "r"(a[0]), "r"(a[1]), "r"(a[2]), "r"(a[3]), "r"(b[0]), "r"(b[1]));
}

// Swizzled byte offset inside a 128-row x 64-col f16 tile (128B rows, SW128 XOR).
DI uint32_t swz(int r, int c8) { return (uint32_t)(r * 128 + ((c8 ^ (r & 7)) << 4)); }

// ---------------- LayerNorm -> f16 (optionally hi/lo split), C = 1024 ----------------
__global__ void __launch_bounds__(256) ln_kernel(
    const float* __restrict__ src, f16* __restrict__ dst_h, f16* __restrict__ dst_l,
    const float* __restrict__ gamma, const float* __restrict__ beta,
    const float* __restrict__ cscale, float sconst)
{
    const int row = blockIdx.x;
    const int t = threadIdx.x;
    const float4* s4 = reinterpret_cast<const float4*>(src) + (size_t)row * 256;
    float4 x = s4[t];
    float sum = x.x + x.y + x.z + x.w;
    float sq  = fmaf(x.x, x.x, fmaf(x.y, x.y, fmaf(x.z, x.z, x.w * x.w)));
#pragma unroll
    for (int o = 16; o; o >>= 1) {
        sum += __shfl_xor_sync(0xffffffffu, sum, o);
        sq  += __shfl_xor_sync(0xffffffffu, sq,  o);
    }
    __shared__ float s_sum[8], s_sq[8];
    if ((t & 31) == 0) { s_sum[t >> 5] = sum; s_sq[t >> 5] = sq; }
    __syncthreads();
    sum = 0.f; sq = 0.f;
#pragma unroll
    for (int i = 0; i < 8; i++) { sum += s_sum[i]; sq += s_sq[i]; }
    const float mu  = sum * (1.f / 1024.f);
    const float var = sq * (1.f / 1024.f) - mu * mu;
    const float rs  = rsqrtf(var + 1e-5f);
    const float sc  = (cscale ? __ldg(cscale + row) : 1.f) * sconst;

    const float4 g = reinterpret_cast<const float4*>(gamma)[t];
    const float4 b = reinterpret_cast<const float4*>(beta)[t];
    float y[4];
    y[0] = ((x.x - mu) * rs * g.x + b.x) * sc;
    y[1] = ((x.y - mu) * rs * g.y + b.y) * sc;
    y[2] = ((x.z - mu) * rs * g.z + b.z) * sc;
    y[3] = ((x.w - mu) * rs * g.w + b.w) * sc;

    __half2 h01 = __floats2half2_rn(y[0], y[1]);
    __half2 h23 = __floats2half2_rn(y[2], y[3]);
    uint2 pk;
    pk.x = *reinterpret_cast<uint32_t*>(&h01);
    pk.y = *reinterpret_cast<uint32_t*>(&h23);
    reinterpret_cast<uint2*>(dst_h + (size_t)row * 1024)[t] = pk;

    if (dst_l) {
        float l0 = y[0] - __half2float(__low2half(h01));
        float l1 = y[1] - __half2float(__high2half(h01));
        float l2 = y[2] - __half2float(__low2half(h23));
        float l3 = y[3] - __half2float(__high2half(h23));
        __half2 l01 = __floats2half2_rn(l0, l1);
        __half2 l23 = __floats2half2_rn(l2, l3);
        uint2 pl;
        pl.x = *reinterpret_cast<uint32_t*>(&l01);
        pl.y = *reinterpret_cast<uint32_t*>(&l23);
        reinterpret_cast<uint2*>(dst_l + (size_t)row * 1024)[t] = pl;
    }
}

// ---------------- f16 transpose: [b][X][C] -> [b][C][X] ----------------
__global__ void transpose_kernel(const f16* __restrict__ src, f16* __restrict__ dst)
{
    __shared__ f16 tile[32][34];
    const int b = blockIdx.z;
    const int x0 = blockIdx.x << 5, c0 = blockIdx.y << 5;
    const f16* s = src + ((size_t)b * Xn + x0) * Cn + c0;
#pragma unroll
    for (int j = 0; j < 4; j++)
        tile[threadIdx.y + j * 8][threadIdx.x] =
            s[(size_t)(threadIdx.y + j * 8) * Cn + threadIdx.x];
    __syncthreads();
    f16* d = dst + ((size_t)b * Cn + c0) * Xn + x0;
#pragma unroll
    for (int j = 0; j < 4; j++)
        d[(size_t)(threadIdx.y + j * 8) * Xn + threadIdx.x] =
            tile[threadIdx.x][threadIdx.y + j * 8];
}

// ---------------- tiled f16 GEMM: 128x128 CTA tile, K-tiles of 64 ----------------
// EPI 0: store f16 scores.  EPI 1: store fp32 (acc + Res).
template <int STAGES, int EPI>
__global__ void __launch_bounds__(256, 2) gemm_kernel(
    const f16* __restrict__ A0, const f16* __restrict__ B0,
    void* __restrict__ Co, const float* __restrict__ Res,
    int M, int N, int K)
{
    extern __shared__ __align__(1024) char smem_raw[];
    constexpr int TILE = 16384;                       // 128x64 f16
    constexpr int SS   = 2 * TILE;
    const int tid = threadIdx.x, lane = tid & 31, warp = tid >> 5;
    const int wm = warp & 3, wn = warp >> 2;          // 4 x 2 warp grid
    const int bN = blockIdx.x, bM = blockIdx.y, bz = blockIdx.z;

    const f16* Ap = A0 + (size_t)bz * M * K + (size_t)bM * 128 * K;
    const f16* Bp = B0 + (size_t)bz * N * K + (size_t)bN * 128 * K;

    const uint32_t sb = (uint32_t)__cvta_generic_to_shared(smem_raw);
    const int KT = K >> 6;

    auto fill = [&](int t) {
        const int k0 = t * 64;
        const uint32_t base = sb + (uint32_t)(t % STAGES) * SS;
#pragma unroll
        for (int i = 0; i < 4; i++) {
            int idx = tid + i * 256; int r = idx >> 3, c8 = idx & 7;
            cp_async16(base + swz(r, c8), Ap + (size_t)r * K + k0 + c8 * 8);
        }
#pragma unroll
        for (int i = 0; i < 4; i++) {
            int idx = tid + i * 256; int r = idx >> 3, c8 = idx & 7;
            cp_async16(base + TILE + swz(r, c8), Bp + (size_t)r * K + k0 + c8 * 8);
        }
        cp_commit();
    };

    float acc[2][8][4];
#pragma unroll
    for (int mt = 0; mt < 2; mt++)
#pragma unroll
        for (int nt = 0; nt < 8; nt++)
#pragma unroll
            for (int i = 0; i < 4; i++) acc[mt][nt][i] = 0.f;

#pragma unroll
    for (int t = 0; t < STAGES - 1; t++) fill(t);

    for (int kt = 0; kt < KT; kt++) {
        cp_wait<STAGES - 2>();
        __syncthreads();
        { const int t = kt + STAGES - 1; if (t < KT) fill(t); else cp_commit(); }

        const uint32_t base = sb + (uint32_t)(kt % STAGES) * SS;
        const uint32_t sA = base;
        const uint32_t sB = base + TILE;
#pragma unroll
        for (int kk = 0; kk < 4; kk++) {
            uint32_t bh[8][2];
#pragma unroll
            for (int np = 0; np < 4; np++) {
                int r = wn * 64 + np * 16 + ((lane >> 4) << 3) + (lane & 7);
                int c8 = kk * 2 + ((lane >> 3) & 1);
                ldsm4(sB + swz(r, c8), bh[2 * np][0], bh[2 * np][1],
                                        bh[2 * np + 1][0], bh[2 * np + 1][1]);
            }
            uint32_t ah[2][4];
#pragma unroll
            for (int mt = 0; mt < 2; mt++) {
                int r = wm * 32 + mt * 16 + (lane & 15);
                int c8 = kk * 2 + (lane >> 4);
                ldsm4(sA + swz(r, c8), ah[mt][0], ah[mt][1], ah[mt][2], ah[mt][3]);
            }
#pragma unroll
            for (int mt = 0; mt < 2; mt++)
#pragma unroll
                for (int nt = 0; nt < 8; nt++)
                    mma16816(acc[mt][nt], ah[mt], bh[nt]);
        }
    }

    const int row0 = bM * 128 + wm * 32;
    const int col0 = bN * 128 + wn * 64;
    const int tr = lane >> 2, tc = (lane & 3) << 1;
    if (EPI == 0) {
        f16* C0 = reinterpret_cast<f16*>(Co) + (size_t)bz * M * N;
#pragma unroll
        for (int mt = 0; mt < 2; mt++)
#pragma unroll
            for (int nt = 0; nt < 8; nt++) {
                int p = row0 + mt * 16 + tr, x = col0 + nt * 8 + tc;
                __half2 a01 = __floats2half2_rn(acc[mt][nt][0], acc[mt][nt][1]);
                __half2 a23 = __floats2half2_rn(acc[mt][nt][2], acc[mt][nt][3]);
                *reinterpret_cast<uint32_t*>(C0 + (size_t)p * N + x) =
                    *reinterpret_cast<uint32_t*>(&a01);
                *reinterpret_cast<uint32_t*>(C0 + (size_t)(p + 8) * N + x) =
                    *reinterpret_cast<uint32_t*>(&a23);
            }
    } else {
        float* C0 = reinterpret_cast<float*>(Co) + (size_t)bz * M * N;
        const float* R0 = Res + (size_t)bz * M * N;
#pragma unroll
        for (int mt = 0; mt < 2; mt++)
#pragma unroll
            for (int nt = 0; nt < 8; nt++) {
                int p = row0 + mt * 16 + tr, x = col0 + nt * 8 + tc;
                float2 r0 = *reinterpret_cast<const float2*>(R0 + (size_t)p * N + x);
                float2 r1 = *reinterpret_cast<const float2*>(R0 + (size_t)(p + 8) * N + x);
                *reinterpret_cast<float2*>(C0 + (size_t)p * N + x) =
                    make_float2(acc[mt][nt][0] + r0.x, acc[mt][nt][1] + r0.y);
                *reinterpret_cast<float2*>(C0 + (size_t)(p + 8) * N + x) =
                    make_float2(acc[mt][nt][2] + r1.x, acc[mt][nt][3] + r1.y);
            }
    }
}

// ---------------- softmax + near-threshold exact repair + sparsify + renorm ----------
DI float blockMax(float v, float* red) {
#pragma unroll
    for (int o = 16; o; o >>= 1) v = fmaxf(v, __shfl_xor_sync(0xffffffffu, v, o));
    __syncthreads();
    if ((threadIdx.x & 31) == 0) red[threadIdx.x >> 5] = v;
    __syncthreads();
    float r = red[0];
#pragma unroll
    for (int i = 1; i < 8; i++) r = fmaxf(r, red[i]);
    return r;
}
DI float blockSum(float v, float* red) {
#pragma unroll
    for (int o = 16; o; o >>= 1) v += __shfl_xor_sync(0xffffffffu, v, o);
    __syncthreads();
    if ((threadIdx.x & 31) == 0) red[threadIdx.x >> 5] = v;
    __syncthreads();
    float r = 0.f;
#pragma unroll
    for (int i = 0; i < 8; i++) r += red[i];
    return r;
}

constexpr int   FCAP  = 1024;
#define DELTA 4e-3f

__global__ void __launch_bounds__(256) softmax_kernel(
    const f16* __restrict__ S,
    const f16* __restrict__ qh, const f16* __restrict__ ql,
    const f16* __restrict__ kh, const f16* __restrict__ kl,
    f16* __restrict__ W)
{
    __shared__ float red[8];
    __shared__ float q_s[1024];
    __shared__ int   nf;
    __shared__ int   fx[FCAP];
    __shared__ float fsn[FCAP];

    const int row = blockIdx.x;            // b*Pn + p
    const int bz  = row >> 10;             // Pn = 1024
    const int t = threadIdx.x;
    const int lane = t & 31, warp = t >> 5;

    // preload exact q row (qh+ql) to smem
    {
        const uint2 ph = reinterpret_cast<const uint2*>(qh + (size_t)row * 1024)[t];
        const uint2 pl = reinterpret_cast<const uint2*>(ql + (size_t)row * 1024)[t];
        __half2 h0 = *reinterpret_cast<const __half2*>(&ph.x);
        __half2 h1 = *reinterpret_cast<const __half2*>(&ph.y);
        __half2 l0 = *reinterpret_cast<const __half2*>(&pl.x);
        __half2 l1 = *reinterpret_cast<const __half2*>(&pl.y);
        q_s[4 * t + 0] = __low2float(h0)  + __low2float(l0);
        q_s[4 * t + 1] = __high2float(h0) + __high2float(l0);
        q_s[4 * t + 2] = __low2float(h1)  + __low2float(l1);
        q_s[4 * t + 3] = __high2float(h1) + __high2float(l1);
    }
    if (t == 0) nf = 0;

    // load f16 scores: 8 x uint2 = 32 values per thread
    const uint2* s2 = reinterpret_cast<const uint2*>(S + (size_t)row * Xn);
    float v[8][4];
    float m = -1e30f;
#pragma unroll
    for (int i = 0; i < 8; i++) {
        uint2 pk = s2[t + i * 256];
        __half2 a = *reinterpret_cast<const __half2*>(&pk.x);
        __half2 b = *reinterpret_cast<const __half2*>(&pk.y);
        v[i][0] = __low2float(a);  v[i][1] = __high2float(a);
        v[i][2] = __low2float(b);  v[i][3] = __high2float(b);
        m = fmaxf(m, fmaxf(fmaxf(v[i][0], v[i][1]), fmaxf(v[i][2], v[i][3])));
    }
    m = blockMax(m, red);                   // also fences q_s / nf writes
    float z = 0.f;
#pragma unroll
    for (int i = 0; i < 8; i++)
#pragma unroll
        for (int j = 0; j < 4; j++) z += __expf(v[i][j] - m);
    z = blockSum(z, red);
    const float thr1 = m + __logf(0.0005f * z);

    // flag entries near the approximate threshold
#pragma unroll
    for (int i = 0; i < 8; i++)
#pragma unroll
        for (int j = 0; j < 4; j++) {
            if (fabsf(v[i][j] - thr1) < DELTA) {
                int sl = atomicAdd(&nf, 1);
                if (sl < FCAP) fx[sl] = 4 * (t + i * 256) + j;
            }
        }
    __syncthreads();
    const int nfc = min(nf, FCAP);

    // exact fp32 recompute of flagged scores: one warp per entry
    for (int e = warp; e < nfc; e += 8) {
        const int x = fx[e];
        const uint2* khp = reinterpret_cast<const uint2*>(kh + ((size_t)bz * Xn + x) * 1024);
        const uint2* klp = reinterpret_cast<const uint2*>(kl + ((size_t)bz * Xn + x) * 1024);
        float sum = 0.f;
#pragma unroll
        for (int jj = 0; jj < 8; jj++) {
            const int c4 = lane + jj * 32;
            const uint2 ph = khp[c4];
            const uint2 pl = klp[c4];
            __half2 h0 = *reinterpret_cast<const __half2*>(&ph.x);
            __half2 h1 = *reinterpret_cast<const __half2*>(&ph.y);
            __half2 l0 = *reinterpret_cast<const __half2*>(&pl.x);
            __half2 l1 = *reinterpret_cast<const __half2*>(&pl.y);
            sum = fmaf(q_s[4 * c4 + 0], __low2float(h0)  + __low2float(l0),  sum);
            sum = fmaf(q_s[4 * c4 + 1], __high2float(h0) + __high2float(l0), sum);
            sum = fmaf(q_s[4 * c4 + 2], __low2float(h1)  + __low2float(l1),  sum);
            sum = fmaf(q_s[4 * c4 + 3], __high2float(h1) + __high2float(l1), sum);
        }
#pragma unroll
        for (int o = 16; o; o >>= 1) sum += __shfl_xor_sync(0xffffffffu, sum, o);
        if (lane == 0) fsn[e] = sum;
    }
    __syncthreads();

    // patch my registers with exact scores
    for (int e = 0; e < nfc; e++) {
        const int x = fx[e];
        const int q4 = x >> 2;
        if ((q4 & 255) == t) v[q4 >> 8][x & 3] = fsn[e];
    }

    // rebuild Z and threshold from patched values (deterministic full reduction)
    float z_p = 0.f;
#pragma unroll
    for (int i = 0; i < 8; i++)
#pragma unroll
        for (int j = 0; j < 4; j++) z_p += __expf(v[i][j] - m);
    z_p = blockSum(z_p, red);
    const float thr = m + __logf(0.0005f * z_p);

    float z2 = 0.f;
#pragma unroll
    for (int i = 0; i < 8; i++)
#pragma unroll
        for (int j = 0; j < 4; j++)
            if (v[i][j] >= thr) z2 += __expf(v[i][j] - m);
    z2 = blockSum(z2, red);
    const float inv = 1.f / z2;

    uint2* wo = reinterpret_cast<uint2*>(W + (size_t)row * Xn);
#pragma unroll
    for (int i = 0; i < 8; i++) {
        float w0 = (v[i][0] >= thr) ? __expf(v[i][0] - m) * inv : 0.f;
        float w1 = (v[i][1] >= thr) ? __expf(v[i][1] - m) * inv : 0.f;
        float w2 = (v[i][2] >= thr) ? __expf(v[i][2] - m) * inv : 0.f;
        float w3 = (v[i][3] >= thr) ? __expf(v[i][3] - m) * inv : 0.f;
        __half2 h01 = __floats2half2_rn(w0, w1);
        __half2 h23 = __floats2half2_rn(w2, w3);
        uint2 pk;
        pk.x = *reinterpret_cast<uint32_t*>(&h01);
        pk.y = *reinterpret_cast<uint32_t*>(&h23);
        wo[t + i * 256] = pk;
    }
}

// ---------------- launch ----------------
extern "C" void kernel_launch(void* const* d_in, const int* in_sizes, int n_in,
                              void* d_out, int out_size)
{
    const float* feat  = (const float*)d_in[0];
    const float* mem_k = (const float*)d_in[1];
    const float* mem_v = (const float*)d_in[2];
    const float* mem_c = (const float*)d_in[3];
    // d_in[4] = mem_attn (unused by reference)
    const float* gq = (const float*)d_in[5];
    const float* bq = (const float*)d_in[6];
    const float* gk = (const float*)d_in[7];
    const float* bk = (const float*)d_in[8];
    const float* gv = (const float*)d_in[9];
    const float* bv = (const float*)d_in[10];
    float* out = (float*)d_out;

    f16 *qh, *ql, *kh, *kl, *v, *vt, *S, *W;
    cudaGetSymbolAddress((void**)&qh, g_qh);
    cudaGetSymbolAddress((void**)&ql, g_ql);
    cudaGetSymbolAddress((void**)&kh, g_kh);
    cudaGetSymbolAddress((void**)&kl, g_kl);
    cudaGetSymbolAddress((void**)&v,  g_v);
    cudaGetSymbolAddress((void**)&vt, g_vt);
    cudaGetSymbolAddress((void**)&S,  g_S);
    cudaGetSymbolAddress((void**)&W,  g_W);

    // side stream + events, created once on the first (non-capturing) call
    static cudaStream_t s2 = nullptr;
    static cudaEvent_t evFork = nullptr, evJoin = nullptr;
    if (!s2) {
        cudaStreamCreateWithFlags(&s2, cudaStreamNonBlocking);
        cudaEventCreateWithFlags(&evFork, cudaEventDisableTiming);
        cudaEventCreateWithFlags(&evJoin, cudaEventDisableTiming);
    }

    // smem: 3 stages x 32KB = 98304 -> 2 CTAs/SM
    const int SM = 3 * 2 * 16384;
    cudaFuncSetAttribute(gemm_kernel<3, 0>, cudaFuncAttributeMaxDynamicSharedMemorySize, SM);
    cudaFuncSetAttribute(gemm_kernel<3, 1>, cudaFuncAttributeMaxDynamicSharedMemorySize, SM);

    // fork: V-path (ln_v + transpose) runs concurrently with the Q/K/score path
    cudaEventRecord(evFork, 0);
    cudaStreamWaitEvent(s2, evFork, 0);
    ln_kernel<<<Bn * Xn, 256, 0, s2>>>(mem_v, v, nullptr, gv, bv, nullptr, 1.f);
    transpose_kernel<<<dim3(Xn / 32, Cn / 32, Bn), dim3(32, 8), 0, s2>>>(v, vt);
    cudaEventRecord(evJoin, s2);

    // main path
    ln_kernel<<<Bn * Pn, 256>>>(feat,  qh, ql, gq, bq, nullptr, S32);
    ln_kernel<<<Bn * Xn, 256>>>(mem_k, kh, kl, gk, bk, mem_c,   S32);

    // S~ = qh @ kh^T  (single fp16 pass, f16 scores; repaired in softmax)
    gemm_kernel<3, 0><<<dim3(Xn / 128, Pn / 128, Bn), 256, SM>>>(
        qh, kh, S, nullptr, Pn, Xn, Cn);

    softmax_kernel<<<Bn * Pn, 256>>>(S, qh, ql, kh, kl, W);

    // join: GEMM2 needs vt from the side stream
    cudaStreamWaitEvent(0, evJoin, 0);

    // out = W @ v^T + feat
    gemm_kernel<3, 1><<<dim3(Cn / 128, Pn / 128, Bn), 256, SM>>>(
        W, vt, out, feat, Pn, Cn, Xn);
}